// round 3
// baseline (speedup 1.0000x reference)
#include <cuda_runtime.h>

// Grouped 1x7 conv (NCHW, groups=2, identical weights per group) + roll(H).
// x: (1,48,56,56) f32, w: (24,96,7) f32, shift: int. out: (1,192,56,56) f32.
// out[g*96+oc][(h+shift)%56][w] = sum_{ic,kw} x[g*24+ic][h][w+kw-3] * w[ic][oc][kw]
//
// Tile: 1 thread = 8 w-outputs x 2 oc, accumulated in 8 packed f32x2 regs.
// fma.rn.f32x2: a = dup(x), b = (w_oc0, w_oc1) via single LDS.64, c = packed acc.

#define Hdim 56
#define Wdim 56
#define HW   3136
#define ICg  24
#define KW   7

typedef unsigned long long u64;

__device__ __forceinline__ u64 dup2(float v) {
    u64 d;
    asm("mov.b64 %0, {%1, %1};" : "=l"(d) : "f"(v));
    return d;
}
__device__ __forceinline__ void fma2(u64& acc, u64 a, u64 b) {
    asm("fma.rn.f32x2 %0, %1, %2, %0;" : "+l"(acc) : "l"(a), "l"(b));
}

__global__ __launch_bounds__(256, 1)
void conv1x7_k3(const float* __restrict__ x, const float* __restrict__ w,
                const int* __restrict__ shift, float* __restrict__ out)
{
    __shared__ float2 sw2[2 * ICg * KW];   // [pi][ic][kw] = (w_oc0, w_oc1)

    const int tid = threadIdx.x;
    const int id  = blockIdx.x * 256 + tid;

    // first combined channel index (c = g*48 + ocpair) touched by this block
    const int c0 = (blockIdx.x * 256) / 392;

    // Stage interleaved weights for combined channels c0 and c0+1:
    // sw2[pi*168 + ic*7 + kw] = ( w[ic][2*oc_base][kw], w[ic][2*oc_base+1][kw] )
    {
        float* swf = (float*)sw2;
        for (int i = tid; i < 672; i += 256) {
            int pi = i / 336;
            int r  = i - pi * 336;
            int ic = r / 14;
            int r2 = r - ic * 14;
            int kw = r2 >> 1;
            int j  = r2 & 1;
            int c  = min(c0 + pi, 95);
            int oc = 2 * (c % 48) + j;
            swf[i] = w[ic * 672 + oc * 7 + kw];
        }
    }
    __syncthreads();

    const int wt = id % 7;          // w-tile 0..6 (w0 = 8*wt)
    int t = id / 7;
    const int h = t % 56;
    t = t / 56;                     // combined c = g*48 + ocp, 0..95
    const int g   = t / 48;
    const int ocp = t - g * 48;
    const int pi  = t - c0;         // 0 or 1

    const int w0  = wt * 8;
    const bool pLo = (wt != 0);     // f4[0] covers w0-4..w0-1 (pad when wt==0)
    const bool pHi = (wt != 6);     // f4[3],f4[4] cover w0+8..w0+15 (pad when wt==6)

    const float* xrow0 = x + (size_t)g * (ICg * HW) + h * Wdim + (w0 - 4);
    const u64*   swq   = (const u64*)(sw2 + pi * ICg * KW);

    u64 acc2[8];
    #pragma unroll
    for (int i = 0; i < 8; i++) acc2[i] = 0ull;

    const float4 z4 = make_float4(0.f, 0.f, 0.f, 0.f);

    #pragma unroll 4
    for (int ic = 0; ic < ICg; ic++) {
        const float4* xp = (const float4*)(xrow0 + ic * HW);
        float4 v0 = pLo ? xp[0] : z4;
        float4 v1 = xp[1];
        float4 v2 = xp[2];
        float4 v3 = pHi ? xp[3] : z4;
        float4 v4 = pHi ? xp[4] : z4;

        float xv[20];
        *(float4*)(xv +  0) = v0;
        *(float4*)(xv +  4) = v1;
        *(float4*)(xv +  8) = v2;
        *(float4*)(xv + 12) = v3;
        *(float4*)(xv + 16) = v4;

        u64 wq[KW];
        #pragma unroll
        for (int k = 0; k < KW; k++) wq[k] = swq[ic * KW + k];

        // duplicate the 14 used window values into packed pairs
        u64 xd[14];
        #pragma unroll
        for (int m = 0; m < 14; m++) xd[m] = dup2(xv[m + 1]);

        #pragma unroll
        for (int i = 0; i < 8; i++) {
            #pragma unroll
            for (int k = 0; k < KW; k++) {
                // x at w = w0+i+k-3  ->  xv[1+i+k]  ->  xd[i+k]
                fma2(acc2[i], xd[i + k], wq[k]);
            }
        }
    }

    // roll along H
    const int s = *shift;
    int ho = (h + s) % Hdim;
    if (ho < 0) ho += Hdim;

    float a0[8], a1[8];
    #pragma unroll
    for (int i = 0; i < 8; i++) {
        float lo, hi;
        asm("mov.b64 {%0, %1}, %2;" : "=f"(lo), "=f"(hi) : "l"(acc2[i]));
        a0[i] = lo; a1[i] = hi;
    }

    float* o0 = out + (size_t)(g * 96 + 2 * ocp + 0) * HW + ho * Wdim + w0;
    float* o1 = out + (size_t)(g * 96 + 2 * ocp + 1) * HW + ho * Wdim + w0;
    ((float4*)o0)[0] = make_float4(a0[0], a0[1], a0[2], a0[3]);
    ((float4*)o0)[1] = make_float4(a0[4], a0[5], a0[6], a0[7]);
    ((float4*)o1)[0] = make_float4(a1[0], a1[1], a1[2], a1[3]);
    ((float4*)o1)[1] = make_float4(a1[4], a1[5], a1[6], a1[7]);
}

extern "C" void kernel_launch(void* const* d_in, const int* in_sizes, int n_in,
                              void* d_out, int out_size)
{
    const float* x     = (const float*)d_in[0];
    const float* w     = (const float*)d_in[1];
    const int*   shift = (const int*)  d_in[2];
    float*       out   = (float*)d_out;

    // 2 groups * 48 ocpairs * 56 rows * 7 wtiles = 37632 threads = 147 * 256
    conv1x7_k3<<<147, 256>>>(x, w, shift, out);
}